// round 3
// baseline (speedup 1.0000x reference)
#include <cuda_runtime.h>
#include <cstdint>

// x: [64, 3, 512, 512] float32
// keep_mask: [64, 32, 32] bool, widened by harness to a 32-bit type (int32 or
//            float32). Either way: nonzero 32-bit word == keep.
// out = x * upsample16(keep_mask)

static constexpr int B = 64;
static constexpr int C = 3;
static constexpr int H = 512;
static constexpr int W = 512;
static constexpr long long N  = (long long)B * C * H * W;  // 50,331,648 floats
static constexpr long long N4 = N / 4;                     // 12,582,912 float4s

__global__ void __launch_bounds__(256) patchmask_kernel(
    const float4* __restrict__ x4,
    const uint32_t* __restrict__ keep,   // 32-bit per mask element
    float4* __restrict__ out4)
{
    long long i = (long long)blockIdx.x * blockDim.x + threadIdx.x;
    if (i >= N4) return;

    long long base = i << 2;               // float index of first of 4 elems
    int w  = (int)(base & (W - 1));        // W = 512 = 2^9
    int h  = (int)((base >> 9) & (H - 1)); // H = 512 = 2^9
    int bc = (int)(base >> 18);            // b*C + c
    int b  = bc / C;                       // C = 3

    // patch coords: 16x16 patches -> 32x32 grid; mask [B,32,32]
    int midx = b * 1024 + ((h >> 4) << 5) + (w >> 4);
    uint32_t m = __ldg(keep + midx);

    float4 v = x4[i];
    if (m == 0u) { v.x = 0.f; v.y = 0.f; v.z = 0.f; v.w = 0.f; }
    out4[i] = v;
}

extern "C" void kernel_launch(void* const* d_in, const int* in_sizes, int n_in,
                              void* d_out, int out_size)
{
    const float4*   x4   = (const float4*)d_in[0];
    const uint32_t* keep = (const uint32_t*)d_in[1];
    float4*         out4 = (float4*)d_out;

    const int threads = 256;
    const long long blocks = (N4 + threads - 1) / threads;  // 49152
    patchmask_kernel<<<(unsigned)blocks, threads>>>(x4, keep, out4);
}

// round 4
// speedup vs baseline: 1.0633x; 1.0633x over previous
#include <cuda_runtime.h>
#include <cstdint>

// x: [64, 3, 512, 512] float32
// keep_mask: [64, 32, 32] -> widened to 32-bit words (nonzero == keep)
// out = x * upsample16(keep_mask)
//
// Optimization: masked patches (35%) produce zeros -> skip reading x there
// (predicated load => no DRAM sectors requested). 32B per thread, one mask
// word per thread (8-float group never crosses a 16-wide patch).

static constexpr int B = 64;
static constexpr int C = 3;
static constexpr int H = 512;
static constexpr int W = 512;
static constexpr long long N  = (long long)B * C * H * W;  // 50,331,648 floats
static constexpr long long N8 = N / 8;                     // 6,291,456 groups of 8

__global__ void __launch_bounds__(256) patchmask_kernel(
    const float4* __restrict__ x4,
    const uint32_t* __restrict__ keep,
    float4* __restrict__ out4)
{
    long long i = (long long)blockIdx.x * blockDim.x + threadIdx.x;
    if (i >= N8) return;

    long long base = i << 3;               // float index of first of 8 elems
    int w  = (int)(base & (W - 1));        // W = 512
    int h  = (int)((base >> 9) & (H - 1)); // H = 512
    int bc = (int)(base >> 18);            // b*C + c
    int b  = bc / C;                       // C = 3

    int midx = b * 1024 + ((h >> 4) << 5) + (w >> 4);
    uint32_t m = __ldg(keep + midx);

    float4 v0 = make_float4(0.f, 0.f, 0.f, 0.f);
    float4 v1 = make_float4(0.f, 0.f, 0.f, 0.f);
    long long j = i << 1;                  // float4 index
    if (m != 0u) {
        v0 = x4[j];
        v1 = x4[j + 1];
    }
    out4[j]     = v0;
    out4[j + 1] = v1;
}

extern "C" void kernel_launch(void* const* d_in, const int* in_sizes, int n_in,
                              void* d_out, int out_size)
{
    const float4*   x4   = (const float4*)d_in[0];
    const uint32_t* keep = (const uint32_t*)d_in[1];
    float4*         out4 = (float4*)d_out;

    const int threads = 256;
    const long long blocks = (N8 + threads - 1) / threads;  // 24576
    patchmask_kernel<<<(unsigned)blocks, threads>>>(x4, keep, out4);
}